// round 16
// baseline (speedup 1.0000x reference)
#include <cuda_runtime.h>
#include <cuda_bf16.h>
#include <math.h>

#define NN 50000
#define EE 800000
#define NEG_SLOPE 0.2f

// ---------------- scratch (no allocations allowed) ----------------
__device__ float    g_ft[NN * 196];     // stride 128 (L0/1) or 196 (L2)
__device__ float    g_h[NN * 128];
__device__ float    g_res2m[NN * 97];   // folded (head-mean) linear residual
__device__ float    g_elerA[NN * 4];    // [n][el0, el1, er0, er1]
__device__ float    g_elerB[NN * 4];
__device__ float    g_wv[3 * 4 * 128];  // per layer: W@al0, W@al1, W@ar0, W@ar1
__device__ unsigned g_ah[NN * 64];
__device__ unsigned g_al[NN * 64];
__device__ unsigned g_bh[4 * 64 * 256]; // regions: 0=W0, 1=W1, 2=W2, 3=fold(res_W2)
__device__ unsigned g_bl[4 * 64 * 256];
__device__ int      g_deg[NN];
__device__ int      g_rowptr[NN + 1];
__device__ int      g_cursor[NN];
__device__ int      g_esrc[EE];

#define BP_STR 256
#define BP_REGION (64 * BP_STR)

// ---------------- helpers ----------------
__device__ __forceinline__ unsigned pack_bf16x2(float x, float y) {
    __nv_bfloat162 t = __floats2bfloat162_rn(x, y);
    return *reinterpret_cast<unsigned*>(&t);
}

__device__ __forceinline__ void mma_bf16(float* c, const unsigned* a, const unsigned* b) {
    asm volatile(
        "mma.sync.aligned.m16n8k16.row.col.f32.bf16.bf16.f32 "
        "{%0,%1,%2,%3}, {%4,%5,%6,%7}, {%8,%9}, {%0,%1,%2,%3};\n"
        : "+f"(c[0]), "+f"(c[1]), "+f"(c[2]), "+f"(c[3])
        : "r"(a[0]), "r"(a[1]), "r"(a[2]), "r"(a[3]), "r"(b[0]), "r"(b[1]));
}

// ---------------- prepack_all: A(x) + B regions 0..3 ----------------
__global__ void prepack_all(const float* __restrict__ x,
                            const float* __restrict__ W0, const float* __restrict__ W1,
                            const float* __restrict__ W2, const float* __restrict__ Wr,
                            unsigned* __restrict__ ah, unsigned* __restrict__ al,
                            unsigned* __restrict__ bh, unsigned* __restrict__ bl) {
    const int totalA = NN * 64;
    int idx = blockIdx.x * blockDim.x + threadIdx.x;
    if (idx < totalA) {
        float2 v = *(const float2*)(x + (long)idx * 2);
        float hx = __bfloat162float(__float2bfloat16_rn(v.x));
        float hy = __bfloat162float(__float2bfloat16_rn(v.y));
        ah[idx] = pack_bf16x2(hx, hy);
        al[idx] = pack_bf16x2(v.x - hx, v.y - hy);
        return;
    }
    int bidx = idx - totalA;
    if (bidx >= 4 * BP_REGION) return;
    int region = bidx / BP_REGION;
    int rem = bidx - region * BP_REGION;
    int kp = rem / BP_STR;
    int c = rem - kp * BP_STR;
    float v0 = 0.f, v1 = 0.f;
    if (region == 0) {
        if (c < 128) { v0 = W0[(2 * kp) * 128 + c]; v1 = W0[(2 * kp + 1) * 128 + c]; }
    } else if (region == 1) {
        if (c < 128) { v0 = W1[(2 * kp) * 128 + c]; v1 = W1[(2 * kp + 1) * 128 + c]; }
    } else if (region == 2) {
        if (c < 194) { v0 = W2[(2 * kp) * 194 + c]; v1 = W2[(2 * kp + 1) * 194 + c]; }
    } else {
        if (c < 97) {
            v0 = 0.5f * (Wr[(2 * kp) * 194 + c]     + Wr[(2 * kp) * 194 + c + 97]);
            v1 = 0.5f * (Wr[(2 * kp + 1) * 194 + c] + Wr[(2 * kp + 1) * 194 + c + 97]);
        }
    }
    float h0 = __bfloat162float(__float2bfloat16_rn(v0));
    float h1 = __bfloat162float(__float2bfloat16_rn(v1));
    bh[bidx] = pack_bf16x2(h0, h1);
    bl[bidx] = pack_bf16x2(v0 - h0, v1 - h1);
}

// ---------------- project_attn: wv[L] = W_L @ {al0,al1,ar0,ar1} ----------------
// el(row) = h . (W[:, :D] @ al0) etc.  One block per layer, 128 threads.
__global__ void project_attn(const float* __restrict__ W0, const float* __restrict__ al0, const float* __restrict__ ar0,
                             const float* __restrict__ W1, const float* __restrict__ al1, const float* __restrict__ ar1,
                             const float* __restrict__ W2, const float* __restrict__ al2, const float* __restrict__ ar2,
                             float* __restrict__ wv) {
    int L = blockIdx.x;
    int k = threadIdx.x;
    const float *W, *al, *ar;
    int D, F;
    if (L == 0)      { W = W0; al = al0; ar = ar0; D = 64; F = 128; }
    else if (L == 1) { W = W1; al = al1; ar = ar1; D = 64; F = 128; }
    else             { W = W2; al = al2; ar = ar2; D = 97; F = 194; }
    float wl0 = 0.f, wl1 = 0.f, wr0 = 0.f, wr1 = 0.f;
    for (int d = 0; d < D; d++) {
        float w0 = W[k * F + d];
        float w1 = W[k * F + D + d];
        float a0 = al[d], a1 = al[D + d];
        float r0 = ar[d], r1 = ar[D + d];
        wl0 += w0 * a0; wr0 += w0 * r0;
        wl1 += w1 * a1; wr1 += w1 * r1;
    }
    float* o = wv + L * 512;
    o[k]       = wl0;
    o[128 + k] = wl1;
    o[256 + k] = wr0;
    o[384 + k] = wr1;
}

// ---------------- el/er for layer 0: warp per node over x ----------------
// el0(n) = x[n] . (W0 @ al0) etc. — reads the RAW INPUT x, not ft.
__global__ void el_er0(const float4* __restrict__ xv, const float* __restrict__ wv,
                       float* __restrict__ eler, int N) {
    int warp = (blockIdx.x * blockDim.x + threadIdx.x) >> 5;
    int lane = threadIdx.x & 31;
    if (warp >= N) return;
    float4 h4 = xv[(long)warp * 32 + lane];
    int c0 = lane * 4;
    float s0, s1, s2, s3;
    {
        float4 w = *(const float4*)(wv + c0);
        s0 = h4.x * w.x + h4.y * w.y + h4.z * w.z + h4.w * w.w;
        w = *(const float4*)(wv + 128 + c0);
        s1 = h4.x * w.x + h4.y * w.y + h4.z * w.z + h4.w * w.w;
        w = *(const float4*)(wv + 256 + c0);
        s2 = h4.x * w.x + h4.y * w.y + h4.z * w.z + h4.w * w.w;
        w = *(const float4*)(wv + 384 + c0);
        s3 = h4.x * w.x + h4.y * w.y + h4.z * w.z + h4.w * w.w;
    }
    #pragma unroll
    for (int o = 16; o > 0; o >>= 1) {
        s0 += __shfl_xor_sync(0xffffffff, s0, o);
        s1 += __shfl_xor_sync(0xffffffff, s1, o);
        s2 += __shfl_xor_sync(0xffffffff, s2, o);
        s3 += __shfl_xor_sync(0xffffffff, s3, o);
    }
    if (lane == 0) *(float4*)(eler + (long)warp * 4) = make_float4(s0, s1, s2, s3);
}

// ================= bf16x3 GEMM, 64x128 tile, 256 threads, 2 CTA/SM =================
#define GBM 64
#define GBN 128
#define A_STR 68
#define B_STR 136
#define SM_AH 0
#define SM_AL (64 * A_STR)
#define SM_BH (2 * 64 * A_STR)
#define SM_BL (2 * 64 * A_STR + 64 * B_STR)
#define GEMM_SMEM_WORDS (2 * 64 * A_STR + 2 * 64 * B_STR)   // 26112 u32 = 104448 B

__global__ void __launch_bounds__(256, 2)
gemm_bf16(const unsigned* __restrict__ gah, const unsigned* __restrict__ gal,
          const unsigned* __restrict__ b1h, const unsigned* __restrict__ b1l,
          int mc1, float* __restrict__ C1, int ldc1,
          const unsigned* __restrict__ b2h, const unsigned* __restrict__ b2l,
          int mc2, float* __restrict__ C2, int ldc2,
          int Nrows, int gx) {
    extern __shared__ unsigned smu[];
    unsigned* Ah = smu + SM_AH;
    unsigned* Al = smu + SM_AL;
    unsigned* Bh = smu + SM_BH;
    unsigned* Bl = smu + SM_BL;

    const int tid = threadIdx.x;
    const int lane = tid & 31;
    const int warp = tid >> 5;      // 0..7
    const int wm = warp & 1;        // 2 warps along M (32 rows each)
    const int wn = warp >> 1;       // 4 warps along N (32 cols each)
    const int row0 = blockIdx.y * GBM;
    const bool second = (blockIdx.x >= gx);
    const int bx = second ? (blockIdx.x - gx) : blockIdx.x;
    float* C = second ? C2 : C1;
    const int ldc = second ? ldc2 : ldc1;
    const int mc = second ? mc2 : mc1;
    const int col0 = bx * GBN;
    const unsigned* bhs = second ? b2h : b1h;
    const unsigned* bls = second ? b2l : b1l;

    #pragma unroll 8
    for (int i = 0; i < 16; i++) {
        int e = tid + i * 256;      // 0..4095
        int r = e >> 6;
        int kp = e & 63;
        int gr = row0 + r;
        unsigned h = 0, l = 0;
        if (gr < Nrows) {
            h = gah[(long)gr * 64 + kp];
            l = gal[(long)gr * 64 + kp];
        }
        Ah[r * A_STR + kp] = h;
        Al[r * A_STR + kp] = l;
    }
    #pragma unroll 8
    for (int i = 0; i < 32; i++) {
        int e = tid + i * 256;      // 0..8191
        int c = e & 127;
        int kp = e >> 7;
        Bh[kp * B_STR + c] = bhs[kp * BP_STR + col0 + c];
        Bl[kp * B_STR + c] = bls[kp * BP_STR + col0 + c];
    }
    __syncthreads();

    float acc[2][4][4];
    #pragma unroll
    for (int mt = 0; mt < 2; mt++)
        #pragma unroll
        for (int nt = 0; nt < 4; nt++)
            #pragma unroll
            for (int j = 0; j < 4; j++) acc[mt][nt][j] = 0.f;

    const int qr = lane >> 2;
    const int qc = lane & 3;

    #pragma unroll
    for (int ks = 0; ks < 8; ks++) {
        const int kg = ks * 8;
        unsigned aH[2][4], aL[2][4];
        #pragma unroll
        for (int mt = 0; mt < 2; mt++) {
            int r = wm * 32 + mt * 16 + qr;
            int b0 = r * A_STR + kg + qc;
            int b1 = (r + 8) * A_STR + kg + qc;
            aH[mt][0] = Ah[b0];     aH[mt][1] = Ah[b1];
            aH[mt][2] = Ah[b0 + 4]; aH[mt][3] = Ah[b1 + 4];
            aL[mt][0] = Al[b0];     aL[mt][1] = Al[b1];
            aL[mt][2] = Al[b0 + 4]; aL[mt][3] = Al[b1 + 4];
        }
        #pragma unroll
        for (int nt = 0; nt < 4; nt++) {
            int c = wn * 32 + nt * 8 + qr;
            int b0 = (kg + qc) * B_STR + c;
            int b1 = (kg + qc + 4) * B_STR + c;
            unsigned bH[2] = { Bh[b0], Bh[b1] };
            unsigned bL[2] = { Bl[b0], Bl[b1] };
            #pragma unroll
            for (int mt = 0; mt < 2; mt++) {
                mma_bf16(acc[mt][nt], aH[mt], bH);
                mma_bf16(acc[mt][nt], aH[mt], bL);
                mma_bf16(acc[mt][nt], aL[mt], bH);
            }
        }
    }

    #pragma unroll
    for (int mt = 0; mt < 2; mt++) {
        int r = row0 + wm * 32 + mt * 16 + qr;
        #pragma unroll
        for (int nt = 0; nt < 4; nt++) {
            int c = col0 + wn * 32 + nt * 8 + qc * 2;
            if (r < Nrows) {
                if (c < mc)     C[(long)r * ldc + c]     = acc[mt][nt][0];
                if (c + 1 < mc) C[(long)r * ldc + c + 1] = acc[mt][nt][1];
            }
            if (r + 8 < Nrows) {
                if (c < mc)     C[(long)(r + 8) * ldc + c]     = acc[mt][nt][2];
                if (c + 1 < mc) C[(long)(r + 8) * ldc + c + 1] = acc[mt][nt][3];
            }
        }
    }
}

// ---------------- CSR build ----------------
__global__ void hist_dst(const int* __restrict__ dst, int* __restrict__ deg, int E) {
    int e = blockIdx.x * blockDim.x + threadIdx.x;
    if (e < E) atomicAdd(&deg[dst[e]], 1);
}

__global__ void exscan_kernel(const int* __restrict__ deg, int* __restrict__ rowptr,
                              int* __restrict__ cursor, int n) {
    __shared__ int sh[1024];
    int t = threadIdx.x;
    const int CH = (n + 1023) / 1024;
    int base = t * CH;
    int sum = 0;
    for (int i = 0; i < CH; i++) {
        int idx = base + i;
        if (idx < n) sum += deg[idx];
    }
    sh[t] = sum;
    __syncthreads();
    for (int off = 1; off < 1024; off <<= 1) {
        int v = (t >= off) ? sh[t - off] : 0;
        __syncthreads();
        sh[t] += v;
        __syncthreads();
    }
    int run = (t == 0) ? 0 : sh[t - 1];
    for (int i = 0; i < CH; i++) {
        int idx = base + i;
        if (idx < n) {
            rowptr[idx] = run;
            cursor[idx] = run;
            run += deg[idx];
        }
    }
    if (t == 1023) rowptr[n] = sh[1023];
}

__global__ void fill_csr(const int* __restrict__ src, const int* __restrict__ dst,
                         int* __restrict__ cursor, int* __restrict__ esrc, int E) {
    int e = blockIdx.x * blockDim.x + threadIdx.x;
    if (e >= E) return;
    int pos = atomicAdd(&cursor[dst[e]], 1);
    esrc[pos] = src[e];
}

// ---------------- fused softmax + aggregate: warp per node ----------------
// eler layout per node: [el0, el1, er0, er1].
// mode 0 (F=128): ELU -> out, emits next-layer bf16 prepack (pah/pal) and,
//                 if wvNext != null, next layer's eler (dot of output row
//                 with the 4 projected attention vectors).
// mode 2 (F=194): head-mean fold epilogue.
__global__ void __launch_bounds__(256)
gat_agg_fused(const int* __restrict__ rowptr, const int* __restrict__ esrc,
              const float4* __restrict__ ftv, int stride4,
              const float* __restrict__ elerIn,
              const float* __restrict__ bias, const float* __restrict__ res,
              float* __restrict__ out,
              unsigned* __restrict__ pah, unsigned* __restrict__ pal,
              const float* __restrict__ wvNext, float* __restrict__ elerOut,
              int F, int D, int mode) {
    __shared__ float s_fin[8][194];
    const int wid = threadIdx.x >> 5;
    const int lane = threadIdx.x & 31;
    const int n = blockIdx.x * 8 + wid;
    if (n >= NN) return;

    const int start = rowptr[n], end = rowptr[n + 1];
    const float4 me = *(const float4*)(elerIn + (long)n * 4);
    const float er0 = me.z, er1 = me.w;
    const int CHN = (F + 3) >> 2;
    const bool secondc = (lane + 32) < CHN;
    const int c0 = lane * 4;
    const int hsel = (c0 + 3 < D) ? 0 : ((c0 >= D) ? 1 : 2);

    float4 a0 = make_float4(0.f, 0.f, 0.f, 0.f);
    float4 a1 = make_float4(0.f, 0.f, 0.f, 0.f);
    float accw0 = 0.f, accw1 = 0.f;

    for (int base = start; base < end; base += 32) {
        int i = base + lane;
        int s = 0;
        float e0 = 0.f, e1 = 0.f;
        if (i < end) {
            s = esrc[i];
            float2 elv = *(const float2*)(elerIn + (long)s * 4);
            float v0 = elv.x + er0; v0 = (v0 > 0.f) ? v0 : NEG_SLOPE * v0;
            float v1 = elv.y + er1; v1 = (v1 > 0.f) ? v1 : NEG_SLOPE * v1;
            e0 = __expf(v0);
            e1 = __expf(v1);
        }
        accw0 += e0;
        accw1 += e1;
        int cnt = min(32, end - base);
        #pragma unroll 4
        for (int j = 0; j < cnt; j++) {
            float w0 = __shfl_sync(0xffffffff, e0, j);
            float w1 = __shfl_sync(0xffffffff, e1, j);
            int sj   = __shfl_sync(0xffffffff, s, j);
            const float4* row = ftv + (long)sj * stride4;
            float4 f0 = row[lane];
            if (hsel != 2) {
                float wa = hsel ? w1 : w0;
                a0.x += f0.x * wa;
                a0.y += f0.y * wa;
                a0.z += f0.z * wa;
                a0.w += f0.w * wa;
            } else {
                a0.x += f0.x * w0;
                a0.y += f0.y * w1;
                a0.z += f0.z * w1;
                a0.w += f0.w * w1;
            }
            if (secondc) {
                float4 f1 = row[lane + 32];
                a1.x += f1.x * w1;
                a1.y += f1.y * w1;
                a1.z += f1.z * w1;
                a1.w += f1.w * w1;
            }
        }
    }

    #pragma unroll
    for (int o = 16; o > 0; o >>= 1) {
        accw0 += __shfl_xor_sync(0xffffffff, accw0, o);
        accw1 += __shfl_xor_sync(0xffffffff, accw1, o);
    }
    const float inv0 = (accw0 > 0.f) ? (1.f / accw0) : 0.f;
    const float inv1 = (accw1 > 0.f) ? (1.f / accw1) : 0.f;

    if (mode == 0) {
        float4 b4 = *(const float4*)(bias + c0);
        float invc = hsel ? inv1 : inv0;
        float4 r;
        r.x = a0.x * invc + b4.x;
        r.y = a0.y * invc + b4.y;
        r.z = a0.z * invc + b4.z;
        r.w = a0.w * invc + b4.w;
        if (res) {
            float4 rv = *(const float4*)(res + (long)n * F + c0);
            r.x += rv.x; r.y += rv.y; r.z += rv.z; r.w += rv.w;
        }
        r.x = (r.x > 0.f) ? r.x : (__expf(r.x) - 1.f);
        r.y = (r.y > 0.f) ? r.y : (__expf(r.y) - 1.f);
        r.z = (r.z > 0.f) ? r.z : (__expf(r.z) - 1.f);
        r.w = (r.w > 0.f) ? r.w : (__expf(r.w) - 1.f);
        *(float4*)(out + (long)n * F + c0) = r;
        {
            float hx = __bfloat162float(__float2bfloat16_rn(r.x));
            float hy = __bfloat162float(__float2bfloat16_rn(r.y));
            float hz = __bfloat162float(__float2bfloat16_rn(r.z));
            float hw = __bfloat162float(__float2bfloat16_rn(r.w));
            pah[(long)n * 64 + lane * 2]     = pack_bf16x2(hx, hy);
            pah[(long)n * 64 + lane * 2 + 1] = pack_bf16x2(hz, hw);
            pal[(long)n * 64 + lane * 2]     = pack_bf16x2(r.x - hx, r.y - hy);
            pal[(long)n * 64 + lane * 2 + 1] = pack_bf16x2(r.z - hz, r.w - hw);
        }
        // ---- next layer's el/er from the output row (zero extra traffic) ----
        if (wvNext) {
            float4 w;
            w = *(const float4*)(wvNext + c0);
            float s0 = r.x * w.x + r.y * w.y + r.z * w.z + r.w * w.w;
            w = *(const float4*)(wvNext + 128 + c0);
            float s1 = r.x * w.x + r.y * w.y + r.z * w.z + r.w * w.w;
            w = *(const float4*)(wvNext + 256 + c0);
            float s2 = r.x * w.x + r.y * w.y + r.z * w.z + r.w * w.w;
            w = *(const float4*)(wvNext + 384 + c0);
            float s3 = r.x * w.x + r.y * w.y + r.z * w.z + r.w * w.w;
            #pragma unroll
            for (int o = 16; o > 0; o >>= 1) {
                s0 += __shfl_xor_sync(0xffffffff, s0, o);
                s1 += __shfl_xor_sync(0xffffffff, s1, o);
                s2 += __shfl_xor_sync(0xffffffff, s2, o);
                s3 += __shfl_xor_sync(0xffffffff, s3, o);
            }
            if (lane == 0)
                *(float4*)(elerOut + (long)n * 4) = make_float4(s0, s1, s2, s3);
        }
    } else {
        float v0[4] = {a0.x, a0.y, a0.z, a0.w};
        float v1[4] = {a1.x, a1.y, a1.z, a1.w};
        #pragma unroll
        for (int jj = 0; jj < 4; jj++) {
            int ch = c0 + jj;
            s_fin[wid][ch] = v0[jj] * ((ch < D) ? inv0 : inv1);
        }
        if (secondc) {
            #pragma unroll
            for (int jj = 0; jj < 4; jj++) {
                int ch = 128 + c0 + jj;
                if (ch < F) s_fin[wid][ch] = v1[jj] * inv1;
            }
        }
        __syncwarp();
        if (n < NN - 1) {
            for (int c = lane; c < 97; c += 32) {
                float bm = 0.5f * (bias[c] + bias[c + 97]);
                out[(long)n * 97 + c] = 0.5f * (s_fin[wid][c] + s_fin[wid][c + 97])
                                        + bm + res[(long)n * 97 + c];
            }
        }
    }
}

// ---------------- host-side orchestration ----------------
static inline int divup(int a, int b) { return (a + b - 1) / b; }

struct Scratch {
    float *ft, *h, *res2m, *elerA, *elerB, *wv;
    unsigned *ah, *al, *bh, *bl;
    int *deg, *rowptr, *cursor, *esrc;
};

static void get_scratch(Scratch& s) {
    cudaGetSymbolAddress((void**)&s.ft, g_ft);
    cudaGetSymbolAddress((void**)&s.h, g_h);
    cudaGetSymbolAddress((void**)&s.res2m, g_res2m);
    cudaGetSymbolAddress((void**)&s.elerA, g_elerA);
    cudaGetSymbolAddress((void**)&s.elerB, g_elerB);
    cudaGetSymbolAddress((void**)&s.wv, g_wv);
    cudaGetSymbolAddress((void**)&s.ah, g_ah);
    cudaGetSymbolAddress((void**)&s.al, g_al);
    cudaGetSymbolAddress((void**)&s.bh, g_bh);
    cudaGetSymbolAddress((void**)&s.bl, g_bl);
    cudaGetSymbolAddress((void**)&s.deg, g_deg);
    cudaGetSymbolAddress((void**)&s.rowptr, g_rowptr);
    cudaGetSymbolAddress((void**)&s.cursor, g_cursor);
    cudaGetSymbolAddress((void**)&s.esrc, g_esrc);
}

extern "C" void kernel_launch(void* const* d_in, const int* in_sizes, int n_in,
                              void* d_out, int out_size) {
    const float* x      = (const float*)d_in[0];
    const int*   src    = (const int*)d_in[1];
    const int*   dst    = (const int*)d_in[2];
    const float* W0     = (const float*)d_in[3];
    const float* al0    = (const float*)d_in[4];
    const float* ar0    = (const float*)d_in[5];
    const float* b0     = (const float*)d_in[6];
    const float* W1     = (const float*)d_in[7];
    const float* al1    = (const float*)d_in[8];
    const float* ar1    = (const float*)d_in[9];
    const float* b1     = (const float*)d_in[10];
    const float* W2     = (const float*)d_in[11];
    const float* al2    = (const float*)d_in[12];
    const float* ar2    = (const float*)d_in[13];
    const float* b2     = (const float*)d_in[14];
    const float* res_W2 = (const float*)d_in[15];
    float* out = (float*)d_out;

    Scratch s;
    get_scratch(s);

    const int N = NN, E = EE;
    const float4* ftv = (const float4*)s.ft;
    const int aggGrid = divup(N, 8);
    const int smem_bytes = GEMM_SMEM_WORDS * 4;
    cudaFuncSetAttribute(gemm_bf16, cudaFuncAttributeMaxDynamicSharedMemorySize, smem_bytes);

    cudaMemsetAsync(s.deg, 0, N * sizeof(int));

    hist_dst<<<divup(E, 256), 256>>>(dst, s.deg, E);                       // 1
    exscan_kernel<<<1, 1024>>>(s.deg, s.rowptr, s.cursor, N);              // 2
    {
        int total = N * 64 + 4 * BP_REGION;
        prepack_all<<<divup(total, 256), 256>>>(x, W0, W1, W2, res_W2,
                                                s.ah, s.al, s.bh, s.bl);   // 3
    }

    // ---- layer 0 (gemm0 = 4th launch -> profiled) ----
    {
        dim3 grid(1, divup(N, GBM));
        gemm_bf16<<<grid, 256, smem_bytes>>>(s.ah, s.al,
                                             s.bh, s.bl, 128, s.ft, 128,
                                             nullptr, nullptr, 0, nullptr, 0, N, 1);
    }
    project_attn<<<3, 128>>>(W0, al0, ar0, W1, al1, ar1, W2, al2, ar2, s.wv);
    fill_csr<<<divup(E, 256), 256>>>(src, dst, s.cursor, s.esrc, E);
    // el0 = x . (W0 @ al0): reads the RAW INPUT x (this was the R15 bug).
    el_er0<<<divup(N * 32, 256), 256>>>((const float4*)x, s.wv, s.elerA, N);
    gat_agg_fused<<<aggGrid, 256>>>(s.rowptr, s.esrc, ftv, 32, s.elerA,
                                    b0, nullptr, s.h, s.ah, s.al,
                                    s.wv + 512, s.elerB, 128, 64, 0);

    // ---- layer 1 (A packed by agg0; eler from agg0 epilogue) ----
    {
        dim3 grid(1, divup(N, GBM));
        gemm_bf16<<<grid, 256, smem_bytes>>>(s.ah, s.al,
                                             s.bh + BP_REGION, s.bl + BP_REGION, 128,
                                             s.ft, 128,
                                             nullptr, nullptr, 0, nullptr, 0, N, 1);
    }
    gat_agg_fused<<<aggGrid, 256>>>(s.rowptr, s.esrc, ftv, 32, s.elerB,
                                    b1, s.h, s.h, s.ah, s.al,
                                    s.wv + 1024, s.elerA, 128, 64, 0);

    // ---- layer 2: dual GEMM; eler from agg1 epilogue ----
    {
        int gx = divup(194, GBN);   // 2
        dim3 grid(gx + 1, divup(N, GBM));
        gemm_bf16<<<grid, 256, smem_bytes>>>(s.ah, s.al,
                                             s.bh + 2 * BP_REGION, s.bl + 2 * BP_REGION,
                                             194, s.ft, 196,
                                             s.bh + 3 * BP_REGION, s.bl + 3 * BP_REGION,
                                             97, s.res2m, 97, N, gx);
    }
    gat_agg_fused<<<aggGrid, 256>>>(s.rowptr, s.esrc, ftv, 49, s.elerA,
                                    b2, s.res2m, out, nullptr, nullptr,
                                    nullptr, nullptr, 194, 97, 2);
}

// round 17
// speedup vs baseline: 1.0053x; 1.0053x over previous
#include <cuda_runtime.h>
#include <cuda_bf16.h>
#include <math.h>

#define NN 50000
#define EE 800000
#define NEG_SLOPE 0.2f

// ---------------- scratch (no allocations allowed) ----------------
__device__ float    g_ft[NN * 196];     // stride 128 (L0/1) or 196 (L2)
__device__ float    g_h[NN * 128];
__device__ float    g_res2m[NN * 97];   // folded (head-mean) linear residual
__device__ float    g_elerA[NN * 4];    // [n][el0, el1, er0, er1]
__device__ float    g_elerB[NN * 4];
__device__ float    g_wv[3 * 4 * 128];  // per layer: W@al0, W@al1, W@ar0, W@ar1
__device__ unsigned g_ah[NN * 64];
__device__ unsigned g_al[NN * 64];
__device__ unsigned g_bh[4 * 64 * 256]; // regions: 0=W0, 1=W1, 2=W2, 3=fold(res_W2)
__device__ unsigned g_bl[4 * 64 * 256];
__device__ int      g_deg[NN];
__device__ int      g_rowptr[NN + 1];
__device__ int      g_cursor[NN];
__device__ int      g_esrc[EE];

#define BP_STR 256
#define BP_REGION (64 * BP_STR)

// ---------------- helpers ----------------
__device__ __forceinline__ unsigned pack_bf16x2(float x, float y) {
    __nv_bfloat162 t = __floats2bfloat162_rn(x, y);
    return *reinterpret_cast<unsigned*>(&t);
}

__device__ __forceinline__ void mma_bf16(float* c, const unsigned* a, const unsigned* b) {
    asm volatile(
        "mma.sync.aligned.m16n8k16.row.col.f32.bf16.bf16.f32 "
        "{%0,%1,%2,%3}, {%4,%5,%6,%7}, {%8,%9}, {%0,%1,%2,%3};\n"
        : "+f"(c[0]), "+f"(c[1]), "+f"(c[2]), "+f"(c[3])
        : "r"(a[0]), "r"(a[1]), "r"(a[2]), "r"(a[3]), "r"(b[0]), "r"(b[1]));
}

// ---------------- prepack_all: A(x) + B regions 0..3 ----------------
__global__ void prepack_all(const float* __restrict__ x,
                            const float* __restrict__ W0, const float* __restrict__ W1,
                            const float* __restrict__ W2, const float* __restrict__ Wr,
                            unsigned* __restrict__ ah, unsigned* __restrict__ al,
                            unsigned* __restrict__ bh, unsigned* __restrict__ bl) {
    const int totalA = NN * 64;
    int idx = blockIdx.x * blockDim.x + threadIdx.x;
    if (idx < totalA) {
        float2 v = *(const float2*)(x + (long)idx * 2);
        float hx = __bfloat162float(__float2bfloat16_rn(v.x));
        float hy = __bfloat162float(__float2bfloat16_rn(v.y));
        ah[idx] = pack_bf16x2(hx, hy);
        al[idx] = pack_bf16x2(v.x - hx, v.y - hy);
        return;
    }
    int bidx = idx - totalA;
    if (bidx >= 4 * BP_REGION) return;
    int region = bidx / BP_REGION;
    int rem = bidx - region * BP_REGION;
    int kp = rem / BP_STR;
    int c = rem - kp * BP_STR;
    float v0 = 0.f, v1 = 0.f;
    if (region == 0) {
        if (c < 128) { v0 = W0[(2 * kp) * 128 + c]; v1 = W0[(2 * kp + 1) * 128 + c]; }
    } else if (region == 1) {
        if (c < 128) { v0 = W1[(2 * kp) * 128 + c]; v1 = W1[(2 * kp + 1) * 128 + c]; }
    } else if (region == 2) {
        if (c < 194) { v0 = W2[(2 * kp) * 194 + c]; v1 = W2[(2 * kp + 1) * 194 + c]; }
    } else {
        if (c < 97) {
            v0 = 0.5f * (Wr[(2 * kp) * 194 + c]     + Wr[(2 * kp) * 194 + c + 97]);
            v1 = 0.5f * (Wr[(2 * kp + 1) * 194 + c] + Wr[(2 * kp + 1) * 194 + c + 97]);
        }
    }
    float h0 = __bfloat162float(__float2bfloat16_rn(v0));
    float h1 = __bfloat162float(__float2bfloat16_rn(v1));
    bh[bidx] = pack_bf16x2(h0, h1);
    bl[bidx] = pack_bf16x2(v0 - h0, v1 - h1);
}

// ---------------- project_attn: wv[L] = W_L @ {al0,al1,ar0,ar1} ----------------
__global__ void project_attn(const float* __restrict__ W0, const float* __restrict__ al0, const float* __restrict__ ar0,
                             const float* __restrict__ W1, const float* __restrict__ al1, const float* __restrict__ ar1,
                             const float* __restrict__ W2, const float* __restrict__ al2, const float* __restrict__ ar2,
                             float* __restrict__ wv) {
    int L = blockIdx.x;
    int k = threadIdx.x;
    const float *W, *al, *ar;
    int D, F;
    if (L == 0)      { W = W0; al = al0; ar = ar0; D = 64; F = 128; }
    else if (L == 1) { W = W1; al = al1; ar = ar1; D = 64; F = 128; }
    else             { W = W2; al = al2; ar = ar2; D = 97; F = 194; }
    float wl0 = 0.f, wl1 = 0.f, wr0 = 0.f, wr1 = 0.f;
    for (int d = 0; d < D; d++) {
        float w0 = W[k * F + d];
        float w1 = W[k * F + D + d];
        float a0 = al[d], a1 = al[D + d];
        float r0 = ar[d], r1 = ar[D + d];
        wl0 += w0 * a0; wr0 += w0 * r0;
        wl1 += w1 * a1; wr1 += w1 * r1;
    }
    float* o = wv + L * 512;
    o[k]       = wl0;
    o[128 + k] = wl1;
    o[256 + k] = wr0;
    o[384 + k] = wr1;
}

// ---------------- el/er for layer 0: warp per node over RAW INPUT x ----------------
__global__ void el_er0(const float4* __restrict__ xv, const float* __restrict__ wv,
                       float* __restrict__ eler, int N) {
    int warp = (blockIdx.x * blockDim.x + threadIdx.x) >> 5;
    int lane = threadIdx.x & 31;
    if (warp >= N) return;
    float4 h4 = xv[(long)warp * 32 + lane];
    int c0 = lane * 4;
    float s0, s1, s2, s3;
    {
        float4 w = *(const float4*)(wv + c0);
        s0 = h4.x * w.x + h4.y * w.y + h4.z * w.z + h4.w * w.w;
        w = *(const float4*)(wv + 128 + c0);
        s1 = h4.x * w.x + h4.y * w.y + h4.z * w.z + h4.w * w.w;
        w = *(const float4*)(wv + 256 + c0);
        s2 = h4.x * w.x + h4.y * w.y + h4.z * w.z + h4.w * w.w;
        w = *(const float4*)(wv + 384 + c0);
        s3 = h4.x * w.x + h4.y * w.y + h4.z * w.z + h4.w * w.w;
    }
    #pragma unroll
    for (int o = 16; o > 0; o >>= 1) {
        s0 += __shfl_xor_sync(0xffffffff, s0, o);
        s1 += __shfl_xor_sync(0xffffffff, s1, o);
        s2 += __shfl_xor_sync(0xffffffff, s2, o);
        s3 += __shfl_xor_sync(0xffffffff, s3, o);
    }
    if (lane == 0) *(float4*)(eler + (long)warp * 4) = make_float4(s0, s1, s2, s3);
}

// ================= bf16x3 GEMM, 128x128 tile, 512 threads (R14 proven config) =================
#define GBM 128
#define GBN 128
#define A_STR 68
#define B_STR 136
#define SM_AH 0
#define SM_AL (128 * A_STR)
#define SM_BH (2 * 128 * A_STR)
#define SM_BL (2 * 128 * A_STR + 64 * B_STR)
#define GEMM_SMEM_WORDS (2 * 128 * A_STR + 2 * 64 * B_STR)   // 139264 B

__global__ void __launch_bounds__(512)
gemm_bf16(const unsigned* __restrict__ gah, const unsigned* __restrict__ gal,
          const unsigned* __restrict__ b1h, const unsigned* __restrict__ b1l,
          int mc1, float* __restrict__ C1, int ldc1,
          const unsigned* __restrict__ b2h, const unsigned* __restrict__ b2l,
          int mc2, float* __restrict__ C2, int ldc2,
          int Nrows, int gx) {
    extern __shared__ unsigned smu[];
    unsigned* Ah = smu + SM_AH;
    unsigned* Al = smu + SM_AL;
    unsigned* Bh = smu + SM_BH;
    unsigned* Bl = smu + SM_BL;

    const int tid = threadIdx.x;
    const int lane = tid & 31;
    const int warp = tid >> 5;      // 0..15
    const int wm = warp & 3;        // 4 warps along M
    const int wn = warp >> 2;       // 4 warps along N
    const int row0 = blockIdx.y * GBM;
    const bool second = (blockIdx.x >= gx);
    const int bx = second ? (blockIdx.x - gx) : blockIdx.x;
    float* C = second ? C2 : C1;
    const int ldc = second ? ldc2 : ldc1;
    const int mc = second ? mc2 : mc1;
    const int col0 = bx * GBN;
    const unsigned* bhs = second ? b2h : b1h;
    const unsigned* bls = second ? b2l : b1l;

    #pragma unroll 8
    for (int i = 0; i < 16; i++) {
        int e = tid + i * 512;
        int r = e >> 6;
        int kp = e & 63;
        int gr = row0 + r;
        unsigned h = 0, l = 0;
        if (gr < Nrows) {
            h = gah[(long)gr * 64 + kp];
            l = gal[(long)gr * 64 + kp];
        }
        Ah[r * A_STR + kp] = h;
        Al[r * A_STR + kp] = l;
    }
    #pragma unroll 8
    for (int i = 0; i < 16; i++) {
        int e = tid + i * 512;
        int c = e & 127;
        int kp = e >> 7;
        Bh[kp * B_STR + c] = bhs[kp * BP_STR + col0 + c];
        Bl[kp * B_STR + c] = bls[kp * BP_STR + col0 + c];
    }
    __syncthreads();

    float acc[2][4][4];
    #pragma unroll
    for (int mt = 0; mt < 2; mt++)
        #pragma unroll
        for (int nt = 0; nt < 4; nt++)
            #pragma unroll
            for (int j = 0; j < 4; j++) acc[mt][nt][j] = 0.f;

    const int qr = lane >> 2;
    const int qc = lane & 3;

    #pragma unroll
    for (int ks = 0; ks < 8; ks++) {
        const int kg = ks * 8;
        unsigned aH[2][4], aL[2][4];
        #pragma unroll
        for (int mt = 0; mt < 2; mt++) {
            int r = wm * 32 + mt * 16 + qr;
            int b0 = r * A_STR + kg + qc;
            int b1 = (r + 8) * A_STR + kg + qc;
            aH[mt][0] = Ah[b0];     aH[mt][1] = Ah[b1];
            aH[mt][2] = Ah[b0 + 4]; aH[mt][3] = Ah[b1 + 4];
            aL[mt][0] = Al[b0];     aL[mt][1] = Al[b1];
            aL[mt][2] = Al[b0 + 4]; aL[mt][3] = Al[b1 + 4];
        }
        #pragma unroll
        for (int nt = 0; nt < 4; nt++) {
            int c = wn * 32 + nt * 8 + qr;
            int b0 = (kg + qc) * B_STR + c;
            int b1 = (kg + qc + 4) * B_STR + c;
            unsigned bH[2] = { Bh[b0], Bh[b1] };
            unsigned bL[2] = { Bl[b0], Bl[b1] };
            #pragma unroll
            for (int mt = 0; mt < 2; mt++) {
                mma_bf16(acc[mt][nt], aH[mt], bH);
                mma_bf16(acc[mt][nt], aH[mt], bL);
                mma_bf16(acc[mt][nt], aL[mt], bH);
            }
        }
    }

    #pragma unroll
    for (int mt = 0; mt < 2; mt++) {
        int r = row0 + wm * 32 + mt * 16 + qr;
        #pragma unroll
        for (int nt = 0; nt < 4; nt++) {
            int c = col0 + wn * 32 + nt * 8 + qc * 2;
            if (r < Nrows) {
                if (c < mc)     C[(long)r * ldc + c]     = acc[mt][nt][0];
                if (c + 1 < mc) C[(long)r * ldc + c + 1] = acc[mt][nt][1];
            }
            if (r + 8 < Nrows) {
                if (c < mc)     C[(long)(r + 8) * ldc + c]     = acc[mt][nt][2];
                if (c + 1 < mc) C[(long)(r + 8) * ldc + c + 1] = acc[mt][nt][3];
            }
        }
    }
}

// ---------------- CSR build ----------------
__global__ void hist_dst(const int* __restrict__ dst, int* __restrict__ deg, int E) {
    int e = blockIdx.x * blockDim.x + threadIdx.x;
    if (e < E) atomicAdd(&deg[dst[e]], 1);
}

__global__ void exscan_kernel(const int* __restrict__ deg, int* __restrict__ rowptr,
                              int* __restrict__ cursor, int n) {
    __shared__ int sh[1024];
    int t = threadIdx.x;
    const int CH = (n + 1023) / 1024;
    int base = t * CH;
    int sum = 0;
    for (int i = 0; i < CH; i++) {
        int idx = base + i;
        if (idx < n) sum += deg[idx];
    }
    sh[t] = sum;
    __syncthreads();
    for (int off = 1; off < 1024; off <<= 1) {
        int v = (t >= off) ? sh[t - off] : 0;
        __syncthreads();
        sh[t] += v;
        __syncthreads();
    }
    int run = (t == 0) ? 0 : sh[t - 1];
    for (int i = 0; i < CH; i++) {
        int idx = base + i;
        if (idx < n) {
            rowptr[idx] = run;
            cursor[idx] = run;
            run += deg[idx];
        }
    }
    if (t == 1023) rowptr[n] = sh[1023];
}

__global__ void fill_csr(const int* __restrict__ src, const int* __restrict__ dst,
                         int* __restrict__ cursor, int* __restrict__ esrc, int E) {
    int e = blockIdx.x * blockDim.x + threadIdx.x;
    if (e >= E) return;
    int pos = atomicAdd(&cursor[dst[e]], 1);
    esrc[pos] = src[e];
}

// ---------------- fused softmax + aggregate: warp per node ----------------
__global__ void __launch_bounds__(256)
gat_agg_fused(const int* __restrict__ rowptr, const int* __restrict__ esrc,
              const float4* __restrict__ ftv, int stride4,
              const float* __restrict__ elerIn,
              const float* __restrict__ bias, const float* __restrict__ res,
              float* __restrict__ out,
              unsigned* __restrict__ pah, unsigned* __restrict__ pal,
              const float* __restrict__ wvNext, float* __restrict__ elerOut,
              int F, int D, int mode) {
    __shared__ float s_fin[8][194];
    const int wid = threadIdx.x >> 5;
    const int lane = threadIdx.x & 31;
    const int n = blockIdx.x * 8 + wid;
    if (n >= NN) return;

    const int start = rowptr[n], end = rowptr[n + 1];
    const float4 me = *(const float4*)(elerIn + (long)n * 4);
    const float er0 = me.z, er1 = me.w;
    const int CHN = (F + 3) >> 2;
    const bool secondc = (lane + 32) < CHN;
    const int c0 = lane * 4;
    const int hsel = (c0 + 3 < D) ? 0 : ((c0 >= D) ? 1 : 2);

    float4 a0 = make_float4(0.f, 0.f, 0.f, 0.f);
    float4 a1 = make_float4(0.f, 0.f, 0.f, 0.f);
    float accw0 = 0.f, accw1 = 0.f;

    for (int base = start; base < end; base += 32) {
        int i = base + lane;
        int s = 0;
        float e0 = 0.f, e1 = 0.f;
        if (i < end) {
            s = esrc[i];
            float2 elv = *(const float2*)(elerIn + (long)s * 4);
            float v0 = elv.x + er0; v0 = (v0 > 0.f) ? v0 : NEG_SLOPE * v0;
            float v1 = elv.y + er1; v1 = (v1 > 0.f) ? v1 : NEG_SLOPE * v1;
            e0 = __expf(v0);
            e1 = __expf(v1);
        }
        accw0 += e0;
        accw1 += e1;
        int cnt = min(32, end - base);
        #pragma unroll 4
        for (int j = 0; j < cnt; j++) {
            float w0 = __shfl_sync(0xffffffff, e0, j);
            float w1 = __shfl_sync(0xffffffff, e1, j);
            int sj   = __shfl_sync(0xffffffff, s, j);
            const float4* row = ftv + (long)sj * stride4;
            float4 f0 = row[lane];
            if (hsel != 2) {
                float wa = hsel ? w1 : w0;
                a0.x += f0.x * wa;
                a0.y += f0.y * wa;
                a0.z += f0.z * wa;
                a0.w += f0.w * wa;
            } else {
                a0.x += f0.x * w0;
                a0.y += f0.y * w1;
                a0.z += f0.z * w1;
                a0.w += f0.w * w1;
            }
            if (secondc) {
                float4 f1 = row[lane + 32];
                a1.x += f1.x * w1;
                a1.y += f1.y * w1;
                a1.z += f1.z * w1;
                a1.w += f1.w * w1;
            }
        }
    }

    #pragma unroll
    for (int o = 16; o > 0; o >>= 1) {
        accw0 += __shfl_xor_sync(0xffffffff, accw0, o);
        accw1 += __shfl_xor_sync(0xffffffff, accw1, o);
    }
    const float inv0 = (accw0 > 0.f) ? (1.f / accw0) : 0.f;
    const float inv1 = (accw1 > 0.f) ? (1.f / accw1) : 0.f;

    if (mode == 0) {
        float4 b4 = *(const float4*)(bias + c0);
        float invc = hsel ? inv1 : inv0;
        float4 r;
        r.x = a0.x * invc + b4.x;
        r.y = a0.y * invc + b4.y;
        r.z = a0.z * invc + b4.z;
        r.w = a0.w * invc + b4.w;
        if (res) {
            float4 rv = *(const float4*)(res + (long)n * F + c0);
            r.x += rv.x; r.y += rv.y; r.z += rv.z; r.w += rv.w;
        }
        r.x = (r.x > 0.f) ? r.x : (__expf(r.x) - 1.f);
        r.y = (r.y > 0.f) ? r.y : (__expf(r.y) - 1.f);
        r.z = (r.z > 0.f) ? r.z : (__expf(r.z) - 1.f);
        r.w = (r.w > 0.f) ? r.w : (__expf(r.w) - 1.f);
        *(float4*)(out + (long)n * F + c0) = r;
        {
            float hx = __bfloat162float(__float2bfloat16_rn(r.x));
            float hy = __bfloat162float(__float2bfloat16_rn(r.y));
            float hz = __bfloat162float(__float2bfloat16_rn(r.z));
            float hw = __bfloat162float(__float2bfloat16_rn(r.w));
            pah[(long)n * 64 + lane * 2]     = pack_bf16x2(hx, hy);
            pah[(long)n * 64 + lane * 2 + 1] = pack_bf16x2(hz, hw);
            pal[(long)n * 64 + lane * 2]     = pack_bf16x2(r.x - hx, r.y - hy);
            pal[(long)n * 64 + lane * 2 + 1] = pack_bf16x2(r.z - hz, r.w - hw);
        }
        if (wvNext) {
            float4 w;
            w = *(const float4*)(wvNext + c0);
            float s0 = r.x * w.x + r.y * w.y + r.z * w.z + r.w * w.w;
            w = *(const float4*)(wvNext + 128 + c0);
            float s1 = r.x * w.x + r.y * w.y + r.z * w.z + r.w * w.w;
            w = *(const float4*)(wvNext + 256 + c0);
            float s2 = r.x * w.x + r.y * w.y + r.z * w.z + r.w * w.w;
            w = *(const float4*)(wvNext + 384 + c0);
            float s3 = r.x * w.x + r.y * w.y + r.z * w.z + r.w * w.w;
            #pragma unroll
            for (int o = 16; o > 0; o >>= 1) {
                s0 += __shfl_xor_sync(0xffffffff, s0, o);
                s1 += __shfl_xor_sync(0xffffffff, s1, o);
                s2 += __shfl_xor_sync(0xffffffff, s2, o);
                s3 += __shfl_xor_sync(0xffffffff, s3, o);
            }
            if (lane == 0)
                *(float4*)(elerOut + (long)n * 4) = make_float4(s0, s1, s2, s3);
        }
    } else {
        float v0[4] = {a0.x, a0.y, a0.z, a0.w};
        float v1[4] = {a1.x, a1.y, a1.z, a1.w};
        #pragma unroll
        for (int jj = 0; jj < 4; jj++) {
            int ch = c0 + jj;
            s_fin[wid][ch] = v0[jj] * ((ch < D) ? inv0 : inv1);
        }
        if (secondc) {
            #pragma unroll
            for (int jj = 0; jj < 4; jj++) {
                int ch = 128 + c0 + jj;
                if (ch < F) s_fin[wid][ch] = v1[jj] * inv1;
            }
        }
        __syncwarp();
        if (n < NN - 1) {
            for (int c = lane; c < 97; c += 32) {
                float bm = 0.5f * (bias[c] + bias[c + 97]);
                out[(long)n * 97 + c] = 0.5f * (s_fin[wid][c] + s_fin[wid][c + 97])
                                        + bm + res[(long)n * 97 + c];
            }
        }
    }
}

// ---------------- host-side orchestration ----------------
static inline int divup(int a, int b) { return (a + b - 1) / b; }

struct Scratch {
    float *ft, *h, *res2m, *elerA, *elerB, *wv;
    unsigned *ah, *al, *bh, *bl;
    int *deg, *rowptr, *cursor, *esrc;
};

static void get_scratch(Scratch& s) {
    cudaGetSymbolAddress((void**)&s.ft, g_ft);
    cudaGetSymbolAddress((void**)&s.h, g_h);
    cudaGetSymbolAddress((void**)&s.res2m, g_res2m);
    cudaGetSymbolAddress((void**)&s.elerA, g_elerA);
    cudaGetSymbolAddress((void**)&s.elerB, g_elerB);
    cudaGetSymbolAddress((void**)&s.wv, g_wv);
    cudaGetSymbolAddress((void**)&s.ah, g_ah);
    cudaGetSymbolAddress((void**)&s.al, g_al);
    cudaGetSymbolAddress((void**)&s.bh, g_bh);
    cudaGetSymbolAddress((void**)&s.bl, g_bl);
    cudaGetSymbolAddress((void**)&s.deg, g_deg);
    cudaGetSymbolAddress((void**)&s.rowptr, g_rowptr);
    cudaGetSymbolAddress((void**)&s.cursor, g_cursor);
    cudaGetSymbolAddress((void**)&s.esrc, g_esrc);
}

extern "C" void kernel_launch(void* const* d_in, const int* in_sizes, int n_in,
                              void* d_out, int out_size) {
    const float* x      = (const float*)d_in[0];
    const int*   src    = (const int*)d_in[1];
    const int*   dst    = (const int*)d_in[2];
    const float* W0     = (const float*)d_in[3];
    const float* al0    = (const float*)d_in[4];
    const float* ar0    = (const float*)d_in[5];
    const float* b0     = (const float*)d_in[6];
    const float* W1     = (const float*)d_in[7];
    const float* al1    = (const float*)d_in[8];
    const float* ar1    = (const float*)d_in[9];
    const float* b1     = (const float*)d_in[10];
    const float* W2     = (const float*)d_in[11];
    const float* al2    = (const float*)d_in[12];
    const float* ar2    = (const float*)d_in[13];
    const float* b2     = (const float*)d_in[14];
    const float* res_W2 = (const float*)d_in[15];
    float* out = (float*)d_out;

    Scratch s;
    get_scratch(s);

    const int N = NN, E = EE;
    const float4* ftv = (const float4*)s.ft;
    const int aggGrid = divup(N, 8);
    const int smem_bytes = GEMM_SMEM_WORDS * 4;
    cudaFuncSetAttribute(gemm_bf16, cudaFuncAttributeMaxDynamicSharedMemorySize, smem_bytes);

    cudaMemsetAsync(s.deg, 0, N * sizeof(int));

    hist_dst<<<divup(E, 256), 256>>>(dst, s.deg, E);                       // 1
    exscan_kernel<<<1, 1024>>>(s.deg, s.rowptr, s.cursor, N);              // 2
    {
        int total = N * 64 + 4 * BP_REGION;
        prepack_all<<<divup(total, 256), 256>>>(x, W0, W1, W2, res_W2,
                                                s.ah, s.al, s.bh, s.bl);   // 3
    }

    // ---- layer 0 (gemm0 = 4th launch -> profiled) ----
    {
        dim3 grid(1, divup(N, GBM));
        gemm_bf16<<<grid, 512, smem_bytes>>>(s.ah, s.al,
                                             s.bh, s.bl, 128, s.ft, 128,
                                             nullptr, nullptr, 0, nullptr, 0, N, 1);
    }
    project_attn<<<3, 128>>>(W0, al0, ar0, W1, al1, ar1, W2, al2, ar2, s.wv);
    fill_csr<<<divup(E, 256), 256>>>(src, dst, s.cursor, s.esrc, E);
    // el0 = x . (W0 @ al0): reads the RAW INPUT x.
    el_er0<<<divup(N * 32, 256), 256>>>((const float4*)x, s.wv, s.elerA, N);
    gat_agg_fused<<<aggGrid, 256>>>(s.rowptr, s.esrc, ftv, 32, s.elerA,
                                    b0, nullptr, s.h, s.ah, s.al,
                                    s.wv + 512, s.elerB, 128, 64, 0);

    // ---- layer 1 (A packed by agg0; eler from agg0 epilogue) ----
    {
        dim3 grid(1, divup(N, GBM));
        gemm_bf16<<<grid, 512, smem_bytes>>>(s.ah, s.al,
                                             s.bh + BP_REGION, s.bl + BP_REGION, 128,
                                             s.ft, 128,
                                             nullptr, nullptr, 0, nullptr, 0, N, 1);
    }
    gat_agg_fused<<<aggGrid, 256>>>(s.rowptr, s.esrc, ftv, 32, s.elerB,
                                    b1, s.h, s.h, s.ah, s.al,
                                    s.wv + 1024, s.elerA, 128, 64, 0);

    // ---- layer 2: dual GEMM; eler from agg1 epilogue ----
    {
        int gx = divup(194, GBN);   // 2
        dim3 grid(gx + 1, divup(N, GBM));
        gemm_bf16<<<grid, 512, smem_bytes>>>(s.ah, s.al,
                                             s.bh + 2 * BP_REGION, s.bl + 2 * BP_REGION,
                                             194, s.ft, 196,
                                             s.bh + 3 * BP_REGION, s.bl + 3 * BP_REGION,
                                             97, s.res2m, 97, N, gx);
    }
    gat_agg_fused<<<aggGrid, 256>>>(s.rowptr, s.esrc, ftv, 49, s.elerA,
                                    b2, s.res2m, out, nullptr, nullptr,
                                    nullptr, nullptr, 194, 97, 2);
}